// round 4
// baseline (speedup 1.0000x reference)
#include <cuda_runtime.h>

typedef unsigned long long ull;

#define BATCH 4096

// ---------------- device scratch (no allocations allowed) ----------------
__device__ float g_h  [BATCH * 512];
__device__ float g_qx [BATCH * 512];
__device__ float g_qW2[512 * 512];
__device__ float g_h2 [BATCH * 512];
__device__ float g_qx2[BATCH * 512];
__device__ float g_scale[512];
__device__ float g_shift[512];
__device__ double g_dsum[3];   // [0]=fq21 sum, [1]=wq sum, [2]=fq22 sum

// ---------------- packed f32x2 helpers (Blackwell FFMA2) ----------------
__device__ __forceinline__ ull pack2(float x, float y) {
    ull r;
    unsigned xu = __float_as_uint(x), yu = __float_as_uint(y);
    asm("mov.b64 %0, {%1, %2};" : "=l"(r) : "r"(xu), "r"(yu));
    return r;
}
__device__ __forceinline__ float2 unpack2(ull v) {
    unsigned lo, hi;
    asm("mov.b64 {%0, %1}, %2;" : "=r"(lo), "=r"(hi) : "l"(v));
    float2 f; f.x = __uint_as_float(lo); f.y = __uint_as_float(hi);
    return f;
}
__device__ __forceinline__ ull ffma2(ull a, ull b, ull c) {
    ull d;
    asm("fma.rn.f32x2 %0, %1, %2, %3;" : "=l"(d) : "l"(a), "l"(b), "l"(c));
    return d;
}
__device__ __forceinline__ ull fadd2(ull a, ull b) {
    ull d;
    asm("add.rn.f32x2 %0, %1, %2;" : "=l"(d) : "l"(a), "l"(b));
    return d;
}

// ---------------- block reduce -> atomic double ----------------
__device__ __forceinline__ void block_sum_to(double* target, float v) {
    __shared__ float red[8];
    const int tid = threadIdx.x;
    #pragma unroll
    for (int o = 16; o; o >>= 1) v += __shfl_xor_sync(0xffffffffu, v, o);
    if ((tid & 31) == 0) red[tid >> 5] = v;
    __syncthreads();
    if (tid == 0) {
        float s = 0.f;
        #pragma unroll
        for (int w = 0; w < 8; w++) s += red[w];
        atomicAdd(target, (double)s);
    }
}

__global__ void init_kernel() {
    g_dsum[0] = 0.0; g_dsum[1] = 0.0; g_dsum[2] = 0.0;
}

// ---------------- GEMM: C[m,n] = relu( sum_k f(A[m,k]) * W[n,k] ) ----------------
// BM=BN=128, BK=16, 256 threads, 8x8 per thread, FFMA2 over m-pairs.
// AFFINE: A element transformed as A*g_scale[k]+g_shift[k] (fused BatchNorm).
template<int KDIM, bool AFFINE>
__global__ __launch_bounds__(256, 2)
void gemm_kernel(const float* __restrict__ Aext, const float* __restrict__ Wext)
{
    const float* __restrict__ A = AFFINE ? (const float*)g_qx  : Aext;
    const float* __restrict__ W = AFFINE ? (const float*)g_qW2 : Wext;
    float*       __restrict__ C = AFFINE ? (float*)g_h2 : (float*)g_h;

    __shared__ __align__(16) float As[16][132];
    __shared__ __align__(16) float Bs[16][132];

    const int tid = threadIdx.x;
    const int tx  = tid & 15;   // n group
    const int ty  = tid >> 4;   // m group
    const int m0  = blockIdx.y * 128;
    const int n0  = blockIdx.x * 128;
    const int N   = 512;

    ull acc[4][8];
    #pragma unroll
    for (int p = 0; p < 4; p++)
        #pragma unroll
        for (int n = 0; n < 8; n++) acc[p][n] = 0ull;

    for (int kt = 0; kt < KDIM; kt += 16) {
        // load A tile (128x16) -> As[k][m], 512 float4 / 256 threads
        #pragma unroll
        for (int l = 0; l < 2; l++) {
            int i = tid + l * 256;
            int row = i >> 2, kq = i & 3;
            float4 av = *(const float4*)(A + (size_t)(m0 + row) * KDIM + kt + kq * 4);
            if (AFFINE) {
                float4 sc = *(const float4*)(g_scale + kt + kq * 4);
                float4 sh = *(const float4*)(g_shift + kt + kq * 4);
                av.x = fmaf(av.x, sc.x, sh.x);
                av.y = fmaf(av.y, sc.y, sh.y);
                av.z = fmaf(av.z, sc.z, sh.z);
                av.w = fmaf(av.w, sc.w, sh.w);
            }
            As[kq * 4 + 0][row] = av.x;
            As[kq * 4 + 1][row] = av.y;
            As[kq * 4 + 2][row] = av.z;
            As[kq * 4 + 3][row] = av.w;
        }
        // load W tile (128x16) -> Bs[k][n]
        #pragma unroll
        for (int l = 0; l < 2; l++) {
            int i = tid + l * 256;
            int row = i >> 2, kq = i & 3;
            float4 bv = *(const float4*)(W + (size_t)(n0 + row) * KDIM + kt + kq * 4);
            Bs[kq * 4 + 0][row] = bv.x;
            Bs[kq * 4 + 1][row] = bv.y;
            Bs[kq * 4 + 2][row] = bv.z;
            Bs[kq * 4 + 3][row] = bv.w;
        }
        __syncthreads();

        #pragma unroll
        for (int k = 0; k < 16; k++) {
            const float4 a0 = *(const float4*)&As[k][ty * 8];
            const float4 a1 = *(const float4*)&As[k][ty * 8 + 4];
            const float4 b0 = *(const float4*)&Bs[k][tx * 8];
            const float4 b1 = *(const float4*)&Bs[k][tx * 8 + 4];
            ull ap[4];
            ap[0] = pack2(a0.x, a0.y);
            ap[1] = pack2(a0.z, a0.w);
            ap[2] = pack2(a1.x, a1.y);
            ap[3] = pack2(a1.z, a1.w);
            float bsv[8] = {b0.x, b0.y, b0.z, b0.w, b1.x, b1.y, b1.z, b1.w};
            #pragma unroll
            for (int n = 0; n < 8; n++) {
                ull br = pack2(bsv[n], bsv[n]);
                #pragma unroll
                for (int p = 0; p < 4; p++)
                    acc[p][n] = ffma2(ap[p], br, acc[p][n]);
            }
        }
        __syncthreads();
    }

    // epilogue: relu + store
    #pragma unroll
    for (int p = 0; p < 4; p++) {
        const int r0 = m0 + ty * 8 + 2 * p;
        float v0[8], v1[8];
        #pragma unroll
        for (int n = 0; n < 8; n++) {
            float2 f = unpack2(acc[p][n]);
            v0[n] = fmaxf(f.x, 0.f);
            v1[n] = fmaxf(f.y, 0.f);
        }
        *(float4*)(C + (size_t)r0 * N + n0 + tx * 8)           = make_float4(v0[0], v0[1], v0[2], v0[3]);
        *(float4*)(C + (size_t)r0 * N + n0 + tx * 8 + 4)       = make_float4(v0[4], v0[5], v0[6], v0[7]);
        *(float4*)(C + (size_t)(r0 + 1) * N + n0 + tx * 8)     = make_float4(v1[0], v1[1], v1[2], v1[3]);
        *(float4*)(C + (size_t)(r0 + 1) * N + n0 + tx * 8 + 4) = make_float4(v1[4], v1[5], v1[6], v1[7]);
    }
}

// ---------------- fq21: dim-8 VQ of h (strided groups) ----------------
// vector (b,c): v_j = h[b, j*64+c], j=0..7.  4 vectors/thread, code pairs via FFMA2.
__global__ __launch_bounds__(256)
void fq21_kernel(const float* __restrict__ E)   // E: [8,512]
{
    __shared__ __align__(16) float sE[8][512];
    __shared__ __align__(16) float sC2[512];
    const int tid = threadIdx.x;
    for (int i = tid; i < 8 * 512; i += 256) ((float*)sE)[i] = E[i];
    __syncthreads();
    for (int e = tid; e < 512; e += 256) {
        float s = 0.f;
        #pragma unroll
        for (int j = 0; j < 8; j++) s = fmaf(sE[j][e], sE[j][e], s);
        sC2[e] = s;
    }
    __syncthreads();

    const int base = blockIdx.x * 1024 + tid;
    ull vr[4][8];
    #pragma unroll
    for (int s = 0; s < 4; s++) {
        const int vid = base + s * 256;
        const int b = vid >> 6, c = vid & 63;
        #pragma unroll
        for (int j = 0; j < 8; j++) {
            float v = g_h[(size_t)b * 512 + j * 64 + c];
            vr[s][j] = pack2(v, v);
        }
    }
    float bestd[4] = {1e30f, 1e30f, 1e30f, 1e30f};
    int   bi[4]    = {0, 0, 0, 0};
    const ull M2 = pack2(-2.f, -2.f);
    for (int u = 0; u < 256; u++) {
        const ull c2p = *(const ull*)&sC2[2 * u];
        ull ep[8];
        #pragma unroll
        for (int j = 0; j < 8; j++) ep[j] = *(const ull*)&sE[j][2 * u];
        #pragma unroll
        for (int s = 0; s < 4; s++) {
            ull a0 = ffma2(vr[s][0], ep[0], 0ull);
            ull a1 = ffma2(vr[s][1], ep[1], 0ull);
            a0 = ffma2(vr[s][2], ep[2], a0);
            a1 = ffma2(vr[s][3], ep[3], a1);
            a0 = ffma2(vr[s][4], ep[4], a0);
            a1 = ffma2(vr[s][5], ep[5], a1);
            a0 = ffma2(vr[s][6], ep[6], a0);
            a1 = ffma2(vr[s][7], ep[7], a1);
            float2 d = unpack2(ffma2(M2, fadd2(a0, a1), c2p));
            if (d.x < bestd[s]) { bestd[s] = d.x; bi[s] = 2 * u; }
            if (d.y < bestd[s]) { bestd[s] = d.y; bi[s] = 2 * u + 1; }
        }
    }
    float lsum = 0.f;
    #pragma unroll
    for (int s = 0; s < 4; s++) {
        const int vid = base + s * 256;
        const int b = vid >> 6, c = vid & 63;
        const int e = bi[s];
        #pragma unroll
        for (int j = 0; j < 8; j++) {
            float v  = unpack2(vr[s][j]).x;
            float dq = sE[j][e] - v;
            lsum = fmaf(dq, dq, lsum);
            g_qx[(size_t)b * 512 + j * 64 + c] = v + dq;   // straight-through forward value
        }
    }
    block_sum_to(&g_dsum[0], lsum);
}

// ---------------- weight VQ of W2 (dim-16 groups) ----------------
// vector (g,c): v_k = W2[g*2+(k&1), c*8+(k>>1)], quantize vs embed_q2 [16,512].
__global__ __launch_bounds__(256)
void wq_kernel(const float* __restrict__ W2, const float* __restrict__ E)
{
    __shared__ __align__(16) float sE[16][512];
    __shared__ __align__(16) float sC2[512];
    const int tid = threadIdx.x;
    for (int i = tid; i < 16 * 512; i += 256) ((float*)sE)[i] = E[i];
    __syncthreads();
    for (int e = tid; e < 512; e += 256) {
        float s = 0.f;
        #pragma unroll
        for (int k = 0; k < 16; k++) s = fmaf(sE[k][e], sE[k][e], s);
        sC2[e] = s;
    }
    __syncthreads();

    const int idx = blockIdx.x * 256 + tid;     // 0..16383
    const int g = idx >> 6, c = idx & 63;
    ull vr[16];
    #pragma unroll
    for (int k = 0; k < 16; k++) {
        float v = W2[(size_t)(g * 2 + (k & 1)) * 512 + c * 8 + (k >> 1)];
        vr[k] = pack2(v, v);
    }
    float bestd = 1e30f; int bi = 0;
    const ull M2 = pack2(-2.f, -2.f);
    for (int u = 0; u < 256; u++) {
        const ull c2p = *(const ull*)&sC2[2 * u];
        ull a0 = 0ull, a1 = 0ull;
        #pragma unroll
        for (int k = 0; k < 16; k += 2) {
            a0 = ffma2(vr[k],     *(const ull*)&sE[k][2 * u],     a0);
            a1 = ffma2(vr[k + 1], *(const ull*)&sE[k + 1][2 * u], a1);
        }
        float2 d = unpack2(ffma2(M2, fadd2(a0, a1), c2p));
        if (d.x < bestd) { bestd = d.x; bi = 2 * u; }
        if (d.y < bestd) { bestd = d.y; bi = 2 * u + 1; }
    }
    float lsum = 0.f;
    #pragma unroll
    for (int k = 0; k < 16; k++) {
        float v  = unpack2(vr[k]).x;
        float dq = sE[k][bi] - v;
        lsum = fmaf(dq, dq, lsum);
        g_qW2[(size_t)(g * 2 + (k & 1)) * 512 + c * 8 + (k >> 1)] = v + dq;
    }
    block_sum_to(&g_dsum[1], lsum);
}

// ---------------- BN stats -> fused scale/shift ----------------
__global__ __launch_bounds__(256)
void bn_kernel(const float* __restrict__ gamma, const float* __restrict__ beta)
{
    __shared__ float ssum[4][64], ssq[4][64];
    const int tid = threadIdx.x;
    const int c  = blockIdx.x * 64 + (tid & 63);
    const int rg = tid >> 6;
    float s = 0.f, s2 = 0.f;
    for (int b = rg; b < BATCH; b += 4) {
        float v = g_qx[(size_t)b * 512 + c];
        s += v;
        s2 = fmaf(v, v, s2);
    }
    ssum[rg][tid & 63] = s;
    ssq [rg][tid & 63] = s2;
    __syncthreads();
    if (rg == 0) {
        const int l = tid & 63;
        float S  = ssum[0][l] + ssum[1][l] + ssum[2][l] + ssum[3][l];
        float S2 = ssq [0][l] + ssq [1][l] + ssq [2][l] + ssq [3][l];
        float mu  = S  * (1.f / BATCH);
        float var = S2 * (1.f / BATCH) - mu * mu;
        float sc  = gamma[c] * rsqrtf(var + 1e-5f);
        g_scale[c] = sc;
        g_shift[c] = fmaf(-mu, sc, beta[c]);
    }
}

// ---------------- fq22: dim-2 VQ of h2 ----------------
// vector (b,c): [h2[b,c], h2[b,256+c]], c in [0,256)
__global__ __launch_bounds__(256)
void fq22_kernel(const float* __restrict__ E)   // E: [2,512]
{
    __shared__ __align__(16) float sm0[512];
    __shared__ __align__(16) float sm1[512];
    __shared__ __align__(16) float sc2[512];
    const int tid = threadIdx.x;
    for (int e = tid; e < 512; e += 256) {
        float e0 = E[e], e1 = E[512 + e];
        sm0[e] = -2.f * e0;
        sm1[e] = -2.f * e1;
        sc2[e] = fmaf(e0, e0, e1 * e1);
    }
    __syncthreads();

    const int base = blockIdx.x * 1024 + tid;
    ull v0r[4], v1r[4];
    #pragma unroll
    for (int s = 0; s < 4; s++) {
        const int vid = base + s * 256;
        const int b = vid >> 8, c = vid & 255;
        float a0 = g_h2[(size_t)b * 512 + c];
        float a1 = g_h2[(size_t)b * 512 + 256 + c];
        v0r[s] = pack2(a0, a0);
        v1r[s] = pack2(a1, a1);
    }
    float bestd[4] = {1e30f, 1e30f, 1e30f, 1e30f};
    int   bi[4]    = {0, 0, 0, 0};
    for (int u = 0; u < 256; u++) {
        const ull m0p = *(const ull*)&sm0[2 * u];
        const ull m1p = *(const ull*)&sm1[2 * u];
        const ull c2p = *(const ull*)&sc2[2 * u];
        #pragma unroll
        for (int s = 0; s < 4; s++) {
            float2 d = unpack2(ffma2(v0r[s], m0p, ffma2(v1r[s], m1p, c2p)));
            if (d.x < bestd[s]) { bestd[s] = d.x; bi[s] = 2 * u; }
            if (d.y < bestd[s]) { bestd[s] = d.y; bi[s] = 2 * u + 1; }
        }
    }
    float lsum = 0.f;
    #pragma unroll
    for (int s = 0; s < 4; s++) {
        const int vid = base + s * 256;
        const int b = vid >> 8, c = vid & 255;
        const int e = bi[s];
        float e0 = -0.5f * sm0[e];   // exact (x2 / x0.5 are exact)
        float e1 = -0.5f * sm1[e];
        float v0 = unpack2(v0r[s]).x;
        float v1 = unpack2(v1r[s]).x;
        float d0 = e0 - v0, d1 = e1 - v1;
        lsum = fmaf(d0, d0, lsum);
        lsum = fmaf(d1, d1, lsum);
        g_qx2[(size_t)b * 512 + c]       = v0 + d0;
        g_qx2[(size_t)b * 512 + 256 + c] = v1 + d1;
    }
    block_sum_to(&g_dsum[2], lsum);
}

// ---------------- final: out = qx2 @ W3^T, plus diff scalar ----------------
__global__ __launch_bounds__(256)
void out_kernel(const float* __restrict__ W3, float* __restrict__ out, int out_size)
{
    __shared__ float sW3[10 * 512];
    const int tid = threadIdx.x;
    for (int i = tid; i < 5120; i += 256) sW3[i] = W3[i];
    __syncthreads();
    const int lane = tid & 31, warp = tid >> 5;
    const int b = blockIdx.x * 8 + warp;
    float p[10];
    #pragma unroll
    for (int k = 0; k < 10; k++) p[k] = 0.f;
    #pragma unroll
    for (int t = 0; t < 16; t++) {
        const int c = t * 32 + lane;
        float v = g_qx2[(size_t)b * 512 + c];
        #pragma unroll
        for (int k = 0; k < 10; k++) p[k] = fmaf(v, sW3[k * 512 + c], p[k]);
    }
    #pragma unroll
    for (int k = 0; k < 10; k++) {
        #pragma unroll
        for (int o = 16; o; o >>= 1) p[k] += __shfl_xor_sync(0xffffffffu, p[k], o);
    }
    if (lane == 0) {
        #pragma unroll
        for (int k = 0; k < 10; k++) out[b * 10 + k] = p[k];
    }
    if (blockIdx.x == 0 && tid == 0 && out_size > BATCH * 10) {
        // diff = mean_f21 + mean_f22 + mean_q2
        double diff = g_dsum[0] * (1.0 / 2097152.0)
                    + g_dsum[2] * (1.0 / 2097152.0)
                    + g_dsum[1] * (1.0 / 262144.0);
        out[BATCH * 10] = (float)diff;
    }
}

// ---------------- launch ----------------
extern "C" void kernel_launch(void* const* d_in, const int* in_sizes, int n_in,
                              void* d_out, int out_size)
{
    const float* x      = (const float*)d_in[0];
    const float* W1     = (const float*)d_in[1];
    const float* W2     = (const float*)d_in[2];
    const float* W3     = (const float*)d_in[3];
    const float* gamma1 = (const float*)d_in[4];
    const float* beta1  = (const float*)d_in[5];
    const float* Ef21   = (const float*)d_in[6];
    const float* Eq2    = (const float*)d_in[7];
    const float* Ef22   = (const float*)d_in[8];
    float* out = (float*)d_out;

    init_kernel<<<1, 1>>>();
    gemm_kernel<784, false><<<dim3(4, 32), 256>>>(x, W1);          // h = relu(x @ W1^T)
    fq21_kernel<<<256, 256>>>(Ef21);                                // h -> qx (+d_f21)
    wq_kernel<<<64, 256>>>(W2, Eq2);                                // W2 -> qW2 (+d2)
    bn_kernel<<<8, 256>>>(gamma1, beta1);                           // scale/shift from qx stats
    gemm_kernel<512, true><<<dim3(4, 32), 256>>>(nullptr, nullptr); // h2 = relu(bn(qx) @ qW2^T)
    fq22_kernel<<<1024, 256>>>(Ef22);                               // h2 -> qx2 (+d_f22)
    out_kernel<<<512, 256>>>(W3, out, out_size);                    // logits + diff scalar
}